// round 13
// baseline (speedup 1.0000x reference)
#include <cuda_runtime.h>

#define NN 65536
#define EE 2097152
#define EPAD (2 * EE + 16 * NN)
#define HID 32
#define NG 8
#define OC 33
#define ISZ 8192

// ---------------- scratch (static device allocations only) ----------------
__device__ int   g_deg[NN];
__device__ float g_dinv[NN];
__device__ int   g_cnt[NN];      // raw dst-degree
__device__ int   g_cnt8[NN];     // pair-equalized, padded to multiple of 8
__device__ int   g_rowptr[NN];   // exclusive scan of padded counts (mult of 8)
__device__ int   g_wp[NN];
__device__ int   g_bsum[64];
__device__ __align__(16) int g_esrc[EPAD];   // src-only edges (norm factored out)
// scalar t values (fp32) and premultiplied gather values u = dinv*t (fp32)
__device__ float g_s1[NN], g_s2[NN], g_s3[NN], g_s4[NN];
__device__ float g_ux[NN + 8], g_u1[NN + 8], g_u2[NN + 8], g_u3[NN + 8], g_u4[NN + 8];
// t buffers (fp32, natural layout)
__device__ __align__(128) float g_H[NN * HID];
__device__ __align__(128) float g_A[NN * HID];
__device__ __align__(128) float g_B[NN * HID];
__device__ __align__(128) float g_C[NN * HID];
__device__ __align__(128) float g_O[NN * HID];
// premultiplied gather buffers u = dinv*t (fp32). Rows >= NN are NEVER
// written -> remain statically zero (pad sentinel src=NN gathers zeros).
__device__ __align__(128) float g_UH[(NN + 8) * HID];
__device__ __align__(128) float g_UA[(NN + 8) * HID];
__device__ __align__(128) float g_UB[(NN + 8) * HID];
__device__ __align__(128) float g_UC[(NN + 8) * HID];

// packed f32x2 add (sm_103a paired-FP32 pipe; PTX-only, ptxas won't auto-fuse)
__device__ __forceinline__ unsigned long long paddx2(unsigned long long a,
                                                     unsigned long long b) {
    unsigned long long r;
    asm("add.rn.f32x2 %0, %1, %2;" : "=l"(r) : "l"(a), "l"(b));
    return r;
}

// ---------------- CSR build ----------------
__global__ void k_zero() {
    int i = blockIdx.x * blockDim.x + threadIdx.x;
    if (i < NN) { g_deg[i] = 0; g_cnt[i] = 0; }
}

__global__ void k_hist(const int* __restrict__ ei) {
    int e = blockIdx.x * blockDim.x + threadIdx.x;
    if (e < EE) {
        atomicAdd(&g_deg[ei[e]], 1);        // degree by src
        atomicAdd(&g_cnt[ei[EE + e]], 1);   // histogram by dst
    }
}

// block-level inclusive scan of pair-equalized padded counts + fused dinv.
// Node pair (2k, 2k+1) both get align8(max(cnt[2k], cnt[2k+1])) slots so the
// dual-node prop loop needs no per-node predication.
__global__ void k_scan1() {
    __shared__ int wsum[32];
    int t = threadIdx.x, b = blockIdx.x;
    int i = b * 1024 + t;
    int lane = t & 31, w = t >> 5;
    int d = g_deg[i];
    g_dinv[i] = (d > 0) ? rsqrtf((float)d) : 0.0f;

    int ca = g_cnt[i];
    int cb = g_cnt[i ^ 1];                  // pair partner (same block)
    int cm = ca > cb ? ca : cb;
    int cntp = (cm + 7) & ~7;
    g_cnt8[i] = cntp;

    int x = cntp;
    #pragma unroll
    for (int o = 1; o < 32; o <<= 1) {
        int y = __shfl_up_sync(0xffffffffu, x, o);
        if (lane >= o) x += y;
    }
    if (lane == 31) wsum[w] = x;
    __syncthreads();
    if (w == 0) {
        int s = wsum[lane];
        #pragma unroll
        for (int o = 1; o < 32; o <<= 1) {
            int y = __shfl_up_sync(0xffffffffu, s, o);
            if (lane >= o) s += y;
        }
        wsum[lane] = s;
    }
    __syncthreads();
    int incl = x + (w > 0 ? wsum[w - 1] : 0);
    g_rowptr[i] = incl;                 // inclusive-within-block (temp)
    if (t == 1023) g_bsum[b] = incl;
}

// finalize rowptr (cross-block prefix inline), fill pad slots, compute u_x
__global__ void k_scan3(const float* __restrict__ x) {
    __shared__ int prefix;
    int i = blockIdx.x * 256 + threadIdx.x;
    if (threadIdx.x == 0) {
        int bchunk = blockIdx.x >> 2;   // 1024-node chunks
        int s = 0;
        for (int j = 0; j < bchunk; j++) s += g_bsum[j];
        prefix = s;
    }
    __syncthreads();
    int excl = g_rowptr[i] - g_cnt8[i] + prefix;   // multiple of 8
    g_rowptr[i] = excl;
    g_wp[i] = excl;
    g_ux[i] = g_dinv[i] * x[i];
    int c = g_cnt[i], cp = g_cnt8[i];
    for (int j = excl + c; j < excl + cp; j++) g_esrc[j] = NN;  // zero-row sentinel
}

__global__ void k_scatter(const int* __restrict__ ei) {
    int e = blockIdx.x * blockDim.x + threadIdx.x;
    if (e < EE) {
        int d = ei[EE + e];
        int pos = atomicAdd(&g_wp[d], 1);
        g_esrc[pos] = ei[e];
    }
}

// ---------------- layer 1 (scalar features, premultiplied gathers) ----------------
// FOUR nodes per warp, 8 lanes each: full lane utilization + 4x overhead amortization.
template <bool PREV>
__global__ void k_sprop(const float* __restrict__ uin,
                        const float* __restrict__ sprev,
                        float* __restrict__ sout,
                        float* __restrict__ usout) {
    int warp = (blockIdx.x * blockDim.x + threadIdx.x) >> 5;
    int lane = threadIdx.x & 31;
    int sub = lane & 7;                      // lane within 8-lane group
    int node = warp * 4 + (lane >> 3);       // group -> node
    int beg = g_rowptr[node], c = g_cnt8[node];
    float acc = 0.0f;
    for (int j = sub * 2; j < c; j += 16) {
        int2 s2 = *reinterpret_cast<const int2*>(g_esrc + beg + j);
        acc += __ldg(&uin[s2.x]) + __ldg(&uin[s2.y]);
    }
    #pragma unroll
    for (int o = 4; o; o >>= 1) acc += __shfl_xor_sync(0xffffffffu, acc, o);
    if (sub == 0) {
        float dd = g_dinv[node];
        float p = -dd * acc;
        float tn = PREV ? (2.0f * p - sprev[node]) : p;
        sout[node] = tn;
        usout[node] = dd * tn;
    }
}

// layer-1 combine + layer-2 init: h = relu(b1 + sum_k s_k*W1[k]); H=h; UH=dinv*h; O = h @ W2[0]
__global__ void __launch_bounds__(256, 6) k_l1init(const float* __restrict__ x,
                                                   const float* __restrict__ W1,
                                                   const float* __restrict__ b1,
                                                   const float* __restrict__ W20) {
    __shared__ float Ws[1024];
    int tid = threadIdx.x;
    for (int j = tid; j < 1024; j += 256) Ws[j] = W20[j];
    __syncthreads();
    int gw = (blockIdx.x * 256 + tid) >> 5;
    int lane = tid & 31;
    float v = b1[lane]
            + x[gw]      * W1[lane]
            + g_s1[gw]   * W1[32 + lane]
            + g_s2[gw]   * W1[64 + lane]
            + g_s3[gw]   * W1[96 + lane]
            + g_s4[gw]   * W1[128 + lane];
    float h = fmaxf(v, 0.0f);
    g_H[gw * HID + lane] = h;
    g_UH[gw * HID + lane] = g_dinv[gw] * h;
    float oacc = 0.0f;
    #pragma unroll
    for (int j = 0; j < 32; j++)
        oacc = fmaf(__shfl_sync(0xffffffffu, h, j), Ws[j * 32 + lane], oacc);
    g_O[gw * HID + lane] = oacc;
}

// ---------------- layers 2/3 (32-wide), TWO nodes per warp ----------------
// Packed-gather inner loop: each edge's 32-feature fp32 row is fetched by a
// HALF-warp as 16 x LDG.64 (float2/lane); lanes 0-15 take edge A, lanes 16-31
// edge B -> one load instruction covers two edges. Accumulation uses packed
// add.rn.f32x2 (no cvt instructions). Per iteration: 16 edges, 8 gather
// instructions, 8 packed adds per accumulator pair.
template <bool PREV>
__global__ void __launch_bounds__(256, 5) k_prop32(const unsigned long long* __restrict__ tin2,
                                                   const float* __restrict__ tprev,
                                                   float* __restrict__ tout,
                                                   float* __restrict__ uout,
                                                   const float* __restrict__ Wk) {
    __shared__ float Ws[1024];
    int tid = threadIdx.x;
    for (int j = tid; j < 1024; j += 256) Ws[j] = Wk[j];
    __syncthreads();
    int warp = (blockIdx.x * 256 + tid) >> 5;
    int g0 = warp * 2, g1 = g0 + 1;
    int lane = tid & 31;
    int lane16 = lane & 15;
    bool hi = lane >= 16;
    const int4* p0 = reinterpret_cast<const int4*>(g_esrc + g_rowptr[g0]);
    const int4* p1 = reinterpret_cast<const int4*>(g_esrc + g_rowptr[g1]);
    int nIter = g_cnt8[g0] >> 3;            // == g_cnt8[g1] >> 3 (pair-equalized)
    unsigned long long acc0 = 0ull, acc1 = 0ull;   // packed f32x2 (+0.0,+0.0)
    for (int it = 0; it < nIter; it++) {
        int4 ea = p0[0], eb = p0[1];        // 8 edges of node g0
        int4 ec = p1[0], ed = p1[1];        // 8 edges of node g1
        p0 += 2; p1 += 2;
        int s0 = hi ? ea.y : ea.x;
        int s1 = hi ? ea.w : ea.z;
        int s2 = hi ? eb.y : eb.x;
        int s3 = hi ? eb.w : eb.z;
        int s4 = hi ? ec.y : ec.x;
        int s5 = hi ? ec.w : ec.z;
        int s6 = hi ? ed.y : ed.x;
        int s7 = hi ? ed.w : ed.z;
        unsigned long long v0 = __ldg(tin2 + s0 * 16 + lane16);
        unsigned long long v1 = __ldg(tin2 + s1 * 16 + lane16);
        unsigned long long v2 = __ldg(tin2 + s2 * 16 + lane16);
        unsigned long long v3 = __ldg(tin2 + s3 * 16 + lane16);
        unsigned long long v4 = __ldg(tin2 + s4 * 16 + lane16);
        unsigned long long v5 = __ldg(tin2 + s5 * 16 + lane16);
        unsigned long long v6 = __ldg(tin2 + s6 * 16 + lane16);
        unsigned long long v7 = __ldg(tin2 + s7 * 16 + lane16);
        acc0 = paddx2(acc0, paddx2(paddx2(v0, v1), paddx2(v2, v3)));
        acc1 = paddx2(acc1, paddx2(paddx2(v4, v5), paddx2(v6, v7)));
    }
    // combine the two half-warps (each summed half of the edges)
    acc0 = paddx2(acc0, __shfl_xor_sync(0xffffffffu, acc0, 16));
    acc1 = paddx2(acc1, __shfl_xor_sync(0xffffffffu, acc1, 16));
    // convert packed (features 2*lane16, 2*lane16+1) -> scalar (feature = lane)
    unsigned long long pk0 = __shfl_sync(0xffffffffu, acc0, lane >> 1);
    unsigned long long pk1 = __shfl_sync(0xffffffffu, acc1, lane >> 1);
    float accs0 = (lane & 1) ? __uint_as_float((unsigned)(pk0 >> 32))
                             : __uint_as_float((unsigned)pk0);
    float accs1 = (lane & 1) ? __uint_as_float((unsigned)(pk1 >> 32))
                             : __uint_as_float((unsigned)pk1);
    float dd0 = g_dinv[g0], dd1 = g_dinv[g1];
    float pr0 = -dd0 * accs0, pr1 = -dd1 * accs1;
    float tn0, tn1;
    if (PREV) {
        tn0 = 2.0f * pr0 - tprev[g0 * HID + lane];
        tn1 = 2.0f * pr1 - tprev[g1 * HID + lane];
    } else {
        tn0 = pr0; tn1 = pr1;
    }
    tout[g0 * HID + lane] = tn0;
    tout[g1 * HID + lane] = tn1;
    uout[g0 * HID + lane] = dd0 * tn0;
    uout[g1 * HID + lane] = dd1 * tn1;
    float o0 = g_O[g0 * HID + lane];
    float o1 = g_O[g1 * HID + lane];
    #pragma unroll
    for (int j = 0; j < 32; j++) {
        float w = Ws[j * 32 + lane];
        o0 = fmaf(__shfl_sync(0xffffffffu, tn0, j), w, o0);
        o1 = fmaf(__shfl_sync(0xffffffffu, tn1, j), w, o1);
    }
    g_O[g0 * HID + lane] = o0;
    g_O[g1 * HID + lane] = o1;
}

// finalize layer L + init layer L+1: h = relu(O + b); H=h; UH=dinv*h; O = h @ Wn0
__global__ void __launch_bounds__(256, 6) k_finit(const float* __restrict__ b,
                                                  const float* __restrict__ Wn0) {
    __shared__ float Ws[1024];
    int tid = threadIdx.x;
    for (int j = tid; j < 1024; j += 256) Ws[j] = Wn0[j];
    __syncthreads();
    int gw = (blockIdx.x * 256 + tid) >> 5;
    int lane = tid & 31;
    float h = fmaxf(g_O[gw * HID + lane] + b[lane], 0.0f);
    g_H[gw * HID + lane] = h;
    g_UH[gw * HID + lane] = g_dinv[gw] * h;
    float oacc = 0.0f;
    #pragma unroll
    for (int j = 0; j < 32; j++)
        oacc = fmaf(__shfl_sync(0xffffffffu, h, j), Ws[j * 32 + lane], oacc);
    g_O[gw * HID + lane] = oacc;
}

// ---------------- final linear: (8, 262144) @ (262144, 33) + bl ----------------
// layer-3 bias b3 folded in (h = O + b3); no separate finalize pass.
__global__ void k_obias(const float* __restrict__ bl, float* __restrict__ out) {
    int i = threadIdx.x;
    if (i < NG * OC) out[i] = bl[i % OC];
}

__global__ void __launch_bounds__(288) k_linear(const float* __restrict__ Wl,
                                                const float* __restrict__ b3,
                                                float* __restrict__ out) {
    __shared__ float Ws[128 * OC];   // 16896 B
    __shared__ float hs[NG * 128];   //  4096 B
    int t = threadIdx.x;
    int i0 = blockIdx.x * 128;
    for (int j = t; j < 128 * OC; j += 288) Ws[j] = Wl[i0 * OC + j];
    for (int j = t; j < NG * 128; j += 288) {
        int g = j >> 7, ii = j & 127;
        hs[j] = g_O[g * (ISZ * HID) + i0 + ii] + b3[(i0 + ii) & 31];
    }
    __syncthreads();
    if (t < NG * OC) {
        int g = t / OC, o = t % OC;
        float acc = 0.0f;
        #pragma unroll 8
        for (int ii = 0; ii < 128; ii++)
            acc = fmaf(hs[g * 128 + ii], Ws[ii * OC + o], acc);
        atomicAdd(&out[g * OC + o], acc);
    }
}

// ---------------- host ----------------
extern "C" void kernel_launch(void* const* d_in, const int* in_sizes, int n_in,
                              void* d_out, int out_size) {
    const float* x  = (const float*)d_in[0];
    const int*   ei = (const int*)  d_in[1];
    const float* W1 = (const float*)d_in[3];
    const float* b1 = (const float*)d_in[4];
    const float* W2 = (const float*)d_in[5];
    const float* b2 = (const float*)d_in[6];
    const float* W3 = (const float*)d_in[7];
    const float* b3 = (const float*)d_in[8];
    const float* Wl = (const float*)d_in[9];
    const float* bl = (const float*)d_in[10];
    float* out = (float*)d_out;

    float *dH, *dA, *dB, *dC;
    float *dS1, *dS2, *dS3, *dS4, *dUx, *dU1, *dU2, *dU3, *dU4;
    unsigned long long *dUH, *dUA, *dUB, *dUC;
    float *dUHf, *dUAf, *dUBf, *dUCf;
    cudaGetSymbolAddress((void**)&dH,  g_H);
    cudaGetSymbolAddress((void**)&dA,  g_A);
    cudaGetSymbolAddress((void**)&dB,  g_B);
    cudaGetSymbolAddress((void**)&dC,  g_C);
    cudaGetSymbolAddress((void**)&dUHf, g_UH);
    cudaGetSymbolAddress((void**)&dUAf, g_UA);
    cudaGetSymbolAddress((void**)&dUBf, g_UB);
    cudaGetSymbolAddress((void**)&dUCf, g_UC);
    dUH = (unsigned long long*)dUHf;
    dUA = (unsigned long long*)dUAf;
    dUB = (unsigned long long*)dUBf;
    dUC = (unsigned long long*)dUCf;
    cudaGetSymbolAddress((void**)&dS1, g_s1);
    cudaGetSymbolAddress((void**)&dS2, g_s2);
    cudaGetSymbolAddress((void**)&dS3, g_s3);
    cudaGetSymbolAddress((void**)&dS4, g_s4);
    cudaGetSymbolAddress((void**)&dUx, g_ux);
    cudaGetSymbolAddress((void**)&dU1, g_u1);
    cudaGetSymbolAddress((void**)&dU2, g_u2);
    cudaGetSymbolAddress((void**)&dU3, g_u3);
    cudaGetSymbolAddress((void**)&dU4, g_u4);

    // CSR build
    k_zero   <<<NN / 256, 256>>>();
    k_hist   <<<EE / 256, 256>>>(ei);
    k_scan1  <<<64, 1024>>>();                              // + pair-max cnt8 + dinv
    k_scan3  <<<NN / 256, 256>>>(x);                        // prefix + pad + u_x
    k_scatter<<<EE / 256, 256>>>(ei);

    // layer 1 (scalar Chebyshev recurrence, 4 nodes/warp)
    k_sprop<false><<<NN / 32, 256>>>(dUx, nullptr, dS1, dU1);
    k_sprop<true> <<<NN / 32, 256>>>(dU1, x,       dS2, dU2);
    k_sprop<true> <<<NN / 32, 256>>>(dU2, dS1,     dS3, dU3);
    k_sprop<true> <<<NN / 32, 256>>>(dU3, dS2,     dS4, dU4);
    k_l1init<<<NN / 8, 256>>>(x, W1, b1, W2);

    // layer 2 (dual-node prop: NN/2 warps -> NN/16 blocks)
    k_prop32<false> <<<NN / 16, 256>>>(dUH, nullptr, dA, dUAf, W2 + 1 * 1024);
    k_prop32<true>  <<<NN / 16, 256>>>(dUA, dH,      dB, dUBf, W2 + 2 * 1024);
    k_prop32<true>  <<<NN / 16, 256>>>(dUB, dA,      dC, dUCf, W2 + 3 * 1024);
    k_prop32<true>  <<<NN / 16, 256>>>(dUC, dB,      dA, dUAf, W2 + 4 * 1024);
    k_finit<<<NN / 8, 256>>>(b2, W3);   // relu + layer-3 init

    // layer 3
    k_prop32<false> <<<NN / 16, 256>>>(dUH, nullptr, dA, dUAf, W3 + 1 * 1024);
    k_prop32<true>  <<<NN / 16, 256>>>(dUA, dH,      dB, dUBf, W3 + 2 * 1024);
    k_prop32<true>  <<<NN / 16, 256>>>(dUB, dA,      dC, dUCf, W3 + 3 * 1024);
    k_prop32<true>  <<<NN / 16, 256>>>(dUC, dB,      dA, dUAf, W3 + 4 * 1024);

    // readout (b3 folded into k_linear)
    k_obias <<<1, 288>>>(bl, out);
    k_linear<<<(ISZ * HID) / 128, 288>>>(Wl, b3, out);
}

// round 14
// speedup vs baseline: 1.0972x; 1.0972x over previous
#include <cuda_runtime.h>
#include <cuda_fp16.h>

#define NN 65536
#define EE 2097152
#define EPAD (2 * EE + 16 * NN)
#define HID 32
#define NG 8
#define OC 33
#define ISZ 8192

// ---------------- scratch (static device allocations only) ----------------
__device__ int   g_deg[NN];
__device__ float g_dinv[NN];
__device__ int   g_cnt[NN];      // raw dst-degree
__device__ int   g_cnt8[NN];     // pair-equalized, padded to multiple of 8
__device__ int   g_rowptr[NN];   // exclusive scan of padded counts (mult of 8)
__device__ int   g_wp[NN];
__device__ int   g_bsum[64];
__device__ __align__(16) int g_esrc[EPAD];   // src-only edges (norm factored out)
// scalar t values (fp32) and premultiplied gather values u = dinv*t (fp32)
__device__ float g_s1[NN], g_s2[NN], g_s3[NN], g_s4[NN];
__device__ float g_ux[NN + 8], g_u1[NN + 8], g_u2[NN + 8], g_u3[NN + 8], g_u4[NN + 8];
__device__ __align__(128) float g_H[NN * HID];
__device__ __align__(128) float g_A[NN * HID];
__device__ __align__(128) float g_B[NN * HID];
__device__ __align__(128) float g_C[NN * HID];
__device__ __align__(128) float g_O[NN * HID];
// fp16 premultiplied gather mirrors: row i < NN holds dinv[i]*t[i]; rows >= NN
// are NEVER written -> remain statically zero-initialized (pad sentinel src=NN)
__device__ __align__(128) __half g_Hh[(NN + 8) * HID];
__device__ __align__(128) __half g_Ah[(NN + 8) * HID];
__device__ __align__(128) __half g_Bh[(NN + 8) * HID];
__device__ __align__(128) __half g_Ch[(NN + 8) * HID];

// ---------------- CSR build ----------------
__global__ void k_zero() {
    int i = blockIdx.x * blockDim.x + threadIdx.x;
    if (i < NN) { g_deg[i] = 0; g_cnt[i] = 0; }
}

__global__ void k_hist(const int* __restrict__ ei) {
    int e = blockIdx.x * blockDim.x + threadIdx.x;
    if (e < EE) {
        atomicAdd(&g_deg[ei[e]], 1);        // degree by src
        atomicAdd(&g_cnt[ei[EE + e]], 1);   // histogram by dst
    }
}

// block-level inclusive scan of pair-equalized padded counts + fused dinv.
// Node pair (2k, 2k+1) both get align8(max(cnt[2k], cnt[2k+1])) slots so the
// dual-node prop loop needs no per-node predication.
__global__ void k_scan1() {
    __shared__ int wsum[32];
    int t = threadIdx.x, b = blockIdx.x;
    int i = b * 1024 + t;
    int lane = t & 31, w = t >> 5;
    int d = g_deg[i];
    g_dinv[i] = (d > 0) ? rsqrtf((float)d) : 0.0f;

    int ca = g_cnt[i];
    int cb = g_cnt[i ^ 1];                  // pair partner (same block)
    int cm = ca > cb ? ca : cb;
    int cntp = (cm + 7) & ~7;
    g_cnt8[i] = cntp;

    int x = cntp;
    #pragma unroll
    for (int o = 1; o < 32; o <<= 1) {
        int y = __shfl_up_sync(0xffffffffu, x, o);
        if (lane >= o) x += y;
    }
    if (lane == 31) wsum[w] = x;
    __syncthreads();
    if (w == 0) {
        int s = wsum[lane];
        #pragma unroll
        for (int o = 1; o < 32; o <<= 1) {
            int y = __shfl_up_sync(0xffffffffu, s, o);
            if (lane >= o) s += y;
        }
        wsum[lane] = s;
    }
    __syncthreads();
    int incl = x + (w > 0 ? wsum[w - 1] : 0);
    g_rowptr[i] = incl;                 // inclusive-within-block (temp)
    if (t == 1023) g_bsum[b] = incl;
}

// finalize rowptr (cross-block prefix inline), fill pad slots, compute u_x
__global__ void k_scan3(const float* __restrict__ x) {
    __shared__ int prefix;
    int i = blockIdx.x * 256 + threadIdx.x;
    if (threadIdx.x == 0) {
        int bchunk = blockIdx.x >> 2;   // 1024-node chunks
        int s = 0;
        for (int j = 0; j < bchunk; j++) s += g_bsum[j];
        prefix = s;
    }
    __syncthreads();
    int excl = g_rowptr[i] - g_cnt8[i] + prefix;   // multiple of 8
    g_rowptr[i] = excl;
    g_wp[i] = excl;
    g_ux[i] = g_dinv[i] * x[i];
    int c = g_cnt[i], cp = g_cnt8[i];
    for (int j = excl + c; j < excl + cp; j++) g_esrc[j] = NN;  // zero-row sentinel
}

__global__ void k_scatter(const int* __restrict__ ei) {
    int e = blockIdx.x * blockDim.x + threadIdx.x;
    if (e < EE) {
        int d = ei[EE + e];
        int pos = atomicAdd(&g_wp[d], 1);
        g_esrc[pos] = ei[e];
    }
}

// ---------------- layer 1 (scalar features, premultiplied gathers) ----------------
// FOUR nodes per warp, 8 lanes each: full lane utilization + 4x overhead amortization.
template <bool PREV>
__global__ void k_sprop(const float* __restrict__ uin,
                        const float* __restrict__ sprev,
                        float* __restrict__ sout,
                        float* __restrict__ usout) {
    int warp = (blockIdx.x * blockDim.x + threadIdx.x) >> 5;
    int lane = threadIdx.x & 31;
    int sub = lane & 7;                      // lane within 8-lane group
    int node = warp * 4 + (lane >> 3);       // group -> node
    int beg = g_rowptr[node], c = g_cnt8[node];
    float acc = 0.0f;
    for (int j = sub * 2; j < c; j += 16) {
        int2 s2 = *reinterpret_cast<const int2*>(g_esrc + beg + j);
        acc += __ldg(&uin[s2.x]) + __ldg(&uin[s2.y]);
    }
    #pragma unroll
    for (int o = 4; o; o >>= 1) acc += __shfl_xor_sync(0xffffffffu, acc, o);
    if (sub == 0) {
        float dd = g_dinv[node];
        float p = -dd * acc;
        float tn = PREV ? (2.0f * p - sprev[node]) : p;
        sout[node] = tn;
        usout[node] = dd * tn;
    }
}

// layer-1 combine + layer-2 init: h = relu(b1 + sum_k s_k*W1[k]); H=h; Hh=dinv*h; O = h @ W2[0]
__global__ void __launch_bounds__(256, 6) k_l1init(const float* __restrict__ x,
                                                   const float* __restrict__ W1,
                                                   const float* __restrict__ b1,
                                                   const float* __restrict__ W20) {
    __shared__ float Ws[1024];
    int tid = threadIdx.x;
    for (int j = tid; j < 1024; j += 256) Ws[j] = W20[j];
    __syncthreads();
    int gw = (blockIdx.x * 256 + tid) >> 5;
    int lane = tid & 31;
    float v = b1[lane]
            + x[gw]      * W1[lane]
            + g_s1[gw]   * W1[32 + lane]
            + g_s2[gw]   * W1[64 + lane]
            + g_s3[gw]   * W1[96 + lane]
            + g_s4[gw]   * W1[128 + lane];
    float h = fmaxf(v, 0.0f);
    g_H[gw * HID + lane] = h;
    g_Hh[gw * HID + lane] = __float2half(g_dinv[gw] * h);
    float oacc = 0.0f;
    #pragma unroll
    for (int j = 0; j < 32; j++)
        oacc = fmaf(__shfl_sync(0xffffffffu, h, j), Ws[j * 32 + lane], oacc);
    g_O[gw * HID + lane] = oacc;
}

// ---------------- layers 2/3 (32-wide), TWO nodes per warp ----------------
// Packed fp16 gather inner loop: each edge's 64B fp16 row is fetched by a
// HALF-warp as 16 x LDG.32 (__half2 = 2 features/lane); lanes 0-15 take edge
// A, lanes 16-31 edge B -> one load instruction covers two edges at the SAME
// bytes/edge as the scalar-fp16 loop. One HADD2 pair-reduce per 2 loads
// halves the cvt count; accumulation is fp32.
template <bool PREV>
__global__ void __launch_bounds__(256, 5) k_prop32(const __half2* __restrict__ tin2,
                                                   const float* __restrict__ tprev,
                                                   float* __restrict__ tout,
                                                   __half* __restrict__ touth,
                                                   const float* __restrict__ Wk) {
    __shared__ float Ws[1024];
    int tid = threadIdx.x;
    for (int j = tid; j < 1024; j += 256) Ws[j] = Wk[j];
    __syncthreads();
    int warp = (blockIdx.x * 256 + tid) >> 5;
    int g0 = warp * 2, g1 = g0 + 1;
    int lane = tid & 31;
    int lane16 = lane & 15;
    bool hi = lane >= 16;
    const int4* p0 = reinterpret_cast<const int4*>(g_esrc + g_rowptr[g0]);
    const int4* p1 = reinterpret_cast<const int4*>(g_esrc + g_rowptr[g1]);
    int nIter = g_cnt8[g0] >> 3;            // == g_cnt8[g1] >> 3 (pair-equalized)
    float ax0 = 0.0f, ay0 = 0.0f, ax1 = 0.0f, ay1 = 0.0f;
    for (int it = 0; it < nIter; it++) {
        int4 ea = p0[0], eb = p0[1];        // 8 edges of node g0 (uniform loads)
        int4 ec = p1[0], ed = p1[1];        // 8 edges of node g1
        p0 += 2; p1 += 2;
        int s0 = hi ? ea.y : ea.x;
        int s1 = hi ? ea.w : ea.z;
        int s2 = hi ? eb.y : eb.x;
        int s3 = hi ? eb.w : eb.z;
        int s4 = hi ? ec.y : ec.x;
        int s5 = hi ? ec.w : ec.z;
        int s6 = hi ? ed.y : ed.x;
        int s7 = hi ? ed.w : ed.z;
        __half2 v0 = __ldg(tin2 + s0 * 16 + lane16);
        __half2 v1 = __ldg(tin2 + s1 * 16 + lane16);
        __half2 v2 = __ldg(tin2 + s2 * 16 + lane16);
        __half2 v3 = __ldg(tin2 + s3 * 16 + lane16);
        __half2 v4 = __ldg(tin2 + s4 * 16 + lane16);
        __half2 v5 = __ldg(tin2 + s5 * 16 + lane16);
        __half2 v6 = __ldg(tin2 + s6 * 16 + lane16);
        __half2 v7 = __ldg(tin2 + s7 * 16 + lane16);
        __half2 h01 = __hadd2(v0, v1), h23 = __hadd2(v2, v3);
        __half2 h45 = __hadd2(v4, v5), h67 = __hadd2(v6, v7);
        float2 f01 = __half22float2(h01), f23 = __half22float2(h23);
        float2 f45 = __half22float2(h45), f67 = __half22float2(h67);
        ax0 += f01.x + f23.x;  ay0 += f01.y + f23.y;
        ax1 += f45.x + f67.x;  ay1 += f45.y + f67.y;
    }
    // combine the two half-warps (each summed half of the edges)
    ax0 += __shfl_xor_sync(0xffffffffu, ax0, 16);
    ay0 += __shfl_xor_sync(0xffffffffu, ay0, 16);
    ax1 += __shfl_xor_sync(0xffffffffu, ax1, 16);
    ay1 += __shfl_xor_sync(0xffffffffu, ay1, 16);
    // redistribute: lane k needs feature k = 2*(k>>1) + (k&1); lane (k>>1)
    // holds it in x (k even) or y (k odd)
    float fx0 = __shfl_sync(0xffffffffu, ax0, lane >> 1);
    float fy0 = __shfl_sync(0xffffffffu, ay0, lane >> 1);
    float fx1 = __shfl_sync(0xffffffffu, ax1, lane >> 1);
    float fy1 = __shfl_sync(0xffffffffu, ay1, lane >> 1);
    float accs0 = (lane & 1) ? fy0 : fx0;
    float accs1 = (lane & 1) ? fy1 : fx1;
    float dd0 = g_dinv[g0], dd1 = g_dinv[g1];
    float pr0 = -dd0 * accs0, pr1 = -dd1 * accs1;
    float tn0, tn1;
    if (PREV) {
        tn0 = 2.0f * pr0 - tprev[g0 * HID + lane];
        tn1 = 2.0f * pr1 - tprev[g1 * HID + lane];
    } else {
        tn0 = pr0; tn1 = pr1;
    }
    tout[g0 * HID + lane] = tn0;
    tout[g1 * HID + lane] = tn1;
    touth[g0 * HID + lane] = __float2half(dd0 * tn0);
    touth[g1 * HID + lane] = __float2half(dd1 * tn1);
    float o0 = g_O[g0 * HID + lane];
    float o1 = g_O[g1 * HID + lane];
    #pragma unroll
    for (int j = 0; j < 32; j++) {
        float w = Ws[j * 32 + lane];
        o0 = fmaf(__shfl_sync(0xffffffffu, tn0, j), w, o0);
        o1 = fmaf(__shfl_sync(0xffffffffu, tn1, j), w, o1);
    }
    g_O[g0 * HID + lane] = o0;
    g_O[g1 * HID + lane] = o1;
}

// finalize layer L + init layer L+1: h = relu(O + b); H=h; Hh=dinv*h; O = h @ Wn0
__global__ void __launch_bounds__(256, 6) k_finit(const float* __restrict__ b,
                                                  const float* __restrict__ Wn0) {
    __shared__ float Ws[1024];
    int tid = threadIdx.x;
    for (int j = tid; j < 1024; j += 256) Ws[j] = Wn0[j];
    __syncthreads();
    int gw = (blockIdx.x * 256 + tid) >> 5;
    int lane = tid & 31;
    float h = fmaxf(g_O[gw * HID + lane] + b[lane], 0.0f);
    g_H[gw * HID + lane] = h;
    g_Hh[gw * HID + lane] = __float2half(g_dinv[gw] * h);
    float oacc = 0.0f;
    #pragma unroll
    for (int j = 0; j < 32; j++)
        oacc = fmaf(__shfl_sync(0xffffffffu, h, j), Ws[j * 32 + lane], oacc);
    g_O[gw * HID + lane] = oacc;
}

// ---------------- final linear: (8, 262144) @ (262144, 33) + bl ----------------
// layer-3 bias b3 folded in (h = O + b3); no separate finalize pass.
__global__ void k_obias(const float* __restrict__ bl, float* __restrict__ out) {
    int i = threadIdx.x;
    if (i < NG * OC) out[i] = bl[i % OC];
}

__global__ void __launch_bounds__(288) k_linear(const float* __restrict__ Wl,
                                                const float* __restrict__ b3,
                                                float* __restrict__ out) {
    __shared__ float Ws[128 * OC];   // 16896 B
    __shared__ float hs[NG * 128];   //  4096 B
    int t = threadIdx.x;
    int i0 = blockIdx.x * 128;
    for (int j = t; j < 128 * OC; j += 288) Ws[j] = Wl[i0 * OC + j];
    for (int j = t; j < NG * 128; j += 288) {
        int g = j >> 7, ii = j & 127;
        hs[j] = g_O[g * (ISZ * HID) + i0 + ii] + b3[(i0 + ii) & 31];
    }
    __syncthreads();
    if (t < NG * OC) {
        int g = t / OC, o = t % OC;
        float acc = 0.0f;
        #pragma unroll 8
        for (int ii = 0; ii < 128; ii++)
            acc = fmaf(hs[g * 128 + ii], Ws[ii * OC + o], acc);
        atomicAdd(&out[g * OC + o], acc);
    }
}

// ---------------- host ----------------
extern "C" void kernel_launch(void* const* d_in, const int* in_sizes, int n_in,
                              void* d_out, int out_size) {
    const float* x  = (const float*)d_in[0];
    const int*   ei = (const int*)  d_in[1];
    const float* W1 = (const float*)d_in[3];
    const float* b1 = (const float*)d_in[4];
    const float* W2 = (const float*)d_in[5];
    const float* b2 = (const float*)d_in[6];
    const float* W3 = (const float*)d_in[7];
    const float* b3 = (const float*)d_in[8];
    const float* Wl = (const float*)d_in[9];
    const float* bl = (const float*)d_in[10];
    float* out = (float*)d_out;

    float *dH, *dA, *dB, *dC;
    float *dS1, *dS2, *dS3, *dS4, *dUx, *dU1, *dU2, *dU3, *dU4;
    __half *dHh, *dAh, *dBh, *dCh;
    cudaGetSymbolAddress((void**)&dH,  g_H);
    cudaGetSymbolAddress((void**)&dA,  g_A);
    cudaGetSymbolAddress((void**)&dB,  g_B);
    cudaGetSymbolAddress((void**)&dC,  g_C);
    cudaGetSymbolAddress((void**)&dHh, g_Hh);
    cudaGetSymbolAddress((void**)&dAh, g_Ah);
    cudaGetSymbolAddress((void**)&dBh, g_Bh);
    cudaGetSymbolAddress((void**)&dCh, g_Ch);
    cudaGetSymbolAddress((void**)&dS1, g_s1);
    cudaGetSymbolAddress((void**)&dS2, g_s2);
    cudaGetSymbolAddress((void**)&dS3, g_s3);
    cudaGetSymbolAddress((void**)&dS4, g_s4);
    cudaGetSymbolAddress((void**)&dUx, g_ux);
    cudaGetSymbolAddress((void**)&dU1, g_u1);
    cudaGetSymbolAddress((void**)&dU2, g_u2);
    cudaGetSymbolAddress((void**)&dU3, g_u3);
    cudaGetSymbolAddress((void**)&dU4, g_u4);

    const __half2 *dHh2 = (const __half2*)dHh;
    const __half2 *dAh2 = (const __half2*)dAh;
    const __half2 *dBh2 = (const __half2*)dBh;
    const __half2 *dCh2 = (const __half2*)dCh;

    // CSR build
    k_zero   <<<NN / 256, 256>>>();
    k_hist   <<<EE / 256, 256>>>(ei);
    k_scan1  <<<64, 1024>>>();                              // + pair-max cnt8 + dinv
    k_scan3  <<<NN / 256, 256>>>(x);                        // prefix + pad + u_x
    k_scatter<<<EE / 256, 256>>>(ei);

    // layer 1 (scalar Chebyshev recurrence, 4 nodes/warp)
    k_sprop<false><<<NN / 32, 256>>>(dUx, nullptr, dS1, dU1);
    k_sprop<true> <<<NN / 32, 256>>>(dU1, x,       dS2, dU2);
    k_sprop<true> <<<NN / 32, 256>>>(dU2, dS1,     dS3, dU3);
    k_sprop<true> <<<NN / 32, 256>>>(dU3, dS2,     dS4, dU4);
    k_l1init<<<NN / 8, 256>>>(x, W1, b1, W2);

    // layer 2 (dual-node prop: NN/2 warps -> NN/16 blocks)
    k_prop32<false> <<<NN / 16, 256>>>(dHh2, nullptr, dA, dAh, W2 + 1 * 1024);
    k_prop32<true>  <<<NN / 16, 256>>>(dAh2, dH,      dB, dBh, W2 + 2 * 1024);
    k_prop32<true>  <<<NN / 16, 256>>>(dBh2, dA,      dC, dCh, W2 + 3 * 1024);
    k_prop32<true>  <<<NN / 16, 256>>>(dCh2, dB,      dA, dAh, W2 + 4 * 1024);
    k_finit<<<NN / 8, 256>>>(b2, W3);   // relu + layer-3 init

    // layer 3
    k_prop32<false> <<<NN / 16, 256>>>(dHh2, nullptr, dA, dAh, W3 + 1 * 1024);
    k_prop32<true>  <<<NN / 16, 256>>>(dAh2, dH,      dB, dBh, W3 + 2 * 1024);
    k_prop32<true>  <<<NN / 16, 256>>>(dBh2, dA,      dC, dCh, W3 + 3 * 1024);
    k_prop32<true>  <<<NN / 16, 256>>>(dCh2, dB,      dA, dAh, W3 + 4 * 1024);

    // readout (b3 folded into k_linear)
    k_obias <<<1, 288>>>(bl, out);
    k_linear<<<(ISZ * HID) / 128, 288>>>(Wl, b3, out);
}

// round 15
// speedup vs baseline: 1.1434x; 1.0421x over previous
#include <cuda_runtime.h>
#include <cuda_fp16.h>

#define NN 65536
#define EE 2097152
#define EPAD (2 * EE + 16 * NN)
#define HID 32
#define NG 8
#define OC 33
#define ISZ 8192

// ---------------- scratch (static device allocations only) ----------------
__device__ int   g_deg[NN];
__device__ float g_dinv[NN];
__device__ int   g_cnt[NN];      // raw dst-degree
__device__ int   g_cnt8[NN];     // pair-equalized, padded to multiple of 8
__device__ int   g_rowptr[NN];   // exclusive scan of padded counts (mult of 8)
__device__ int   g_wp[NN];
__device__ int   g_bsum[64];
__device__ __align__(16) int g_esrc[EPAD];   // src-only edges (norm factored out)
// scalar t values (fp32) and premultiplied gather values u = dinv*t (fp32)
__device__ float g_s1[NN], g_s2[NN], g_s3[NN], g_s4[NN];
__device__ float g_ux[NN + 8], g_u1[NN + 8], g_u2[NN + 8], g_u3[NN + 8], g_u4[NN + 8];
__device__ __align__(128) float g_H[NN * HID];
__device__ __align__(128) float g_A[NN * HID];
__device__ __align__(128) float g_B[NN * HID];
__device__ __align__(128) float g_C[NN * HID];
__device__ __align__(128) float g_O[NN * HID];
// fp16 premultiplied gather mirrors: row i < NN holds dinv[i]*t[i]; rows >= NN
// are NEVER written -> remain statically zero-initialized (pad sentinel src=NN)
__device__ __align__(128) __half g_Hh[(NN + 8) * HID];
__device__ __align__(128) __half g_Ah[(NN + 8) * HID];
__device__ __align__(128) __half g_Bh[(NN + 8) * HID];
__device__ __align__(128) __half g_Ch[(NN + 8) * HID];

// ---------------- CSR build ----------------
__global__ void k_zero() {
    int i = blockIdx.x * blockDim.x + threadIdx.x;
    if (i < NN) { g_deg[i] = 0; g_cnt[i] = 0; }
}

__global__ void k_hist(const int* __restrict__ ei) {
    int e = blockIdx.x * blockDim.x + threadIdx.x;
    if (e < EE) {
        atomicAdd(&g_deg[ei[e]], 1);        // degree by src
        atomicAdd(&g_cnt[ei[EE + e]], 1);   // histogram by dst
    }
}

// block-level inclusive scan of pair-equalized padded counts + fused dinv.
// Node pair (2k, 2k+1) both get align8(max(cnt[2k], cnt[2k+1])) slots so the
// dual-node prop loop needs no per-node predication.
__global__ void k_scan1() {
    __shared__ int wsum[32];
    int t = threadIdx.x, b = blockIdx.x;
    int i = b * 1024 + t;
    int lane = t & 31, w = t >> 5;
    int d = g_deg[i];
    g_dinv[i] = (d > 0) ? rsqrtf((float)d) : 0.0f;

    int ca = g_cnt[i];
    int cb = g_cnt[i ^ 1];                  // pair partner (same block)
    int cm = ca > cb ? ca : cb;
    int cntp = (cm + 7) & ~7;
    g_cnt8[i] = cntp;

    int x = cntp;
    #pragma unroll
    for (int o = 1; o < 32; o <<= 1) {
        int y = __shfl_up_sync(0xffffffffu, x, o);
        if (lane >= o) x += y;
    }
    if (lane == 31) wsum[w] = x;
    __syncthreads();
    if (w == 0) {
        int s = wsum[lane];
        #pragma unroll
        for (int o = 1; o < 32; o <<= 1) {
            int y = __shfl_up_sync(0xffffffffu, s, o);
            if (lane >= o) s += y;
        }
        wsum[lane] = s;
    }
    __syncthreads();
    int incl = x + (w > 0 ? wsum[w - 1] : 0);
    g_rowptr[i] = incl;                 // inclusive-within-block (temp)
    if (t == 1023) g_bsum[b] = incl;
}

// finalize rowptr (cross-block prefix inline), fill pad slots, compute u_x
__global__ void k_scan3(const float* __restrict__ x) {
    __shared__ int prefix;
    int i = blockIdx.x * 256 + threadIdx.x;
    if (threadIdx.x == 0) {
        int bchunk = blockIdx.x >> 2;   // 1024-node chunks
        int s = 0;
        for (int j = 0; j < bchunk; j++) s += g_bsum[j];
        prefix = s;
    }
    __syncthreads();
    int excl = g_rowptr[i] - g_cnt8[i] + prefix;   // multiple of 8
    g_rowptr[i] = excl;
    g_wp[i] = excl;
    g_ux[i] = g_dinv[i] * x[i];
    int c = g_cnt[i], cp = g_cnt8[i];
    for (int j = excl + c; j < excl + cp; j++) g_esrc[j] = NN;  // zero-row sentinel
}

__global__ void k_scatter(const int* __restrict__ ei) {
    int e = blockIdx.x * blockDim.x + threadIdx.x;
    if (e < EE) {
        int d = ei[EE + e];
        int pos = atomicAdd(&g_wp[d], 1);
        g_esrc[pos] = ei[e];
    }
}

// ---------------- layer 1 (scalar features, premultiplied gathers) ----------------
// FOUR nodes per warp, 8 lanes each; int4 edge loads (4 edges/lane/iter).
template <bool PREV>
__global__ void k_sprop(const float* __restrict__ uin,
                        const float* __restrict__ sprev,
                        float* __restrict__ sout,
                        float* __restrict__ usout) {
    int warp = (blockIdx.x * blockDim.x + threadIdx.x) >> 5;
    int lane = threadIdx.x & 31;
    int sub = lane & 7;                      // lane within 8-lane group
    int node = warp * 4 + (lane >> 3);       // group -> node
    int beg = g_rowptr[node], c = g_cnt8[node];
    float acc = 0.0f;
    for (int j = sub * 4; j < c; j += 32) {
        int4 s4 = *reinterpret_cast<const int4*>(g_esrc + beg + j);
        acc += (__ldg(&uin[s4.x]) + __ldg(&uin[s4.y]))
             + (__ldg(&uin[s4.z]) + __ldg(&uin[s4.w]));
    }
    #pragma unroll
    for (int o = 4; o; o >>= 1) acc += __shfl_xor_sync(0xffffffffu, acc, o);
    if (sub == 0) {
        float dd = g_dinv[node];
        float p = -dd * acc;
        float tn = PREV ? (2.0f * p - sprev[node]) : p;
        sout[node] = tn;
        usout[node] = dd * tn;
    }
}

// layer-1 combine + layer-2 init: h = relu(b1 + sum_k s_k*W1[k]); H=h; Hh=dinv*h; O = h @ W2[0]
__global__ void __launch_bounds__(256, 6) k_l1init(const float* __restrict__ x,
                                                   const float* __restrict__ W1,
                                                   const float* __restrict__ b1,
                                                   const float* __restrict__ W20) {
    __shared__ float Ws[1024];
    int tid = threadIdx.x;
    for (int j = tid; j < 1024; j += 256) Ws[j] = W20[j];
    __syncthreads();
    int gw = (blockIdx.x * 256 + tid) >> 5;
    int lane = tid & 31;
    float v = b1[lane]
            + x[gw]      * W1[lane]
            + g_s1[gw]   * W1[32 + lane]
            + g_s2[gw]   * W1[64 + lane]
            + g_s3[gw]   * W1[96 + lane]
            + g_s4[gw]   * W1[128 + lane];
    float h = fmaxf(v, 0.0f);
    g_H[gw * HID + lane] = h;
    g_Hh[gw * HID + lane] = __float2half(g_dinv[gw] * h);
    float oacc = 0.0f;
    #pragma unroll
    for (int j = 0; j < 32; j++)
        oacc = fmaf(__shfl_sync(0xffffffffu, h, j), Ws[j * 32 + lane], oacc);
    g_O[gw * HID + lane] = oacc;
}

// ---------------- layers 2/3 (32-wide), TWO nodes per warp ----------------
// Quarter-warp packed fp16 gathers: each edge's 64B fp16 row is fetched by
// EIGHT lanes as 8 x LDG.64 (uint2 = 2 x half2 = 4 features/lane); the four
// 8-lane quarters of the warp take four different edges -> one gather
// instruction covers FOUR edges. Edge indices are read per-quarter as
// broadcast LDG.32 (no selects). Bytes/edge unchanged vs R14; gather
// instruction count halved again.
template <bool PREV>
__global__ void __launch_bounds__(256, 5) k_prop32(const uint2* __restrict__ tin4,
                                                   const float* __restrict__ tprev,
                                                   float* __restrict__ tout,
                                                   __half* __restrict__ touth,
                                                   const float* __restrict__ Wk) {
    __shared__ float Ws[1024];
    int tid = threadIdx.x;
    for (int j = tid; j < 1024; j += 256) Ws[j] = Wk[j];
    __syncthreads();
    int warp = (blockIdx.x * 256 + tid) >> 5;
    int g0 = warp * 2, g1 = g0 + 1;
    int lane = tid & 31;
    int q = lane >> 3;                       // quarter id: which edge of 4
    int sub = lane & 7;                      // uint2 index within 32-feature row
    const int* e0 = g_esrc + g_rowptr[g0];
    const int* e1 = g_esrc + g_rowptr[g1];
    int nIter = g_cnt8[g0] >> 3;             // == g_cnt8[g1] >> 3 (pair-equalized)
    float a0x = 0.f, a0y = 0.f, a0z = 0.f, a0w = 0.f;
    float a1x = 0.f, a1y = 0.f, a1z = 0.f, a1w = 0.f;
    for (int it = 0; it < nIter; it++) {
        int sA0 = __ldg(e0 + q);             // edges 0..3 of g0 (broadcast/quarter)
        int sB0 = __ldg(e0 + 4 + q);         // edges 4..7 of g0
        int sA1 = __ldg(e1 + q);
        int sB1 = __ldg(e1 + 4 + q);
        e0 += 8; e1 += 8;
        uint2 vA0 = __ldg(tin4 + sA0 * 8 + sub);
        uint2 vB0 = __ldg(tin4 + sB0 * 8 + sub);
        uint2 vA1 = __ldg(tin4 + sA1 * 8 + sub);
        uint2 vB1 = __ldg(tin4 + sB1 * 8 + sub);
        __half2 lo0 = __hadd2(*reinterpret_cast<__half2*>(&vA0.x),
                              *reinterpret_cast<__half2*>(&vB0.x));
        __half2 hi0 = __hadd2(*reinterpret_cast<__half2*>(&vA0.y),
                              *reinterpret_cast<__half2*>(&vB0.y));
        __half2 lo1 = __hadd2(*reinterpret_cast<__half2*>(&vA1.x),
                              *reinterpret_cast<__half2*>(&vB1.x));
        __half2 hi1 = __hadd2(*reinterpret_cast<__half2*>(&vA1.y),
                              *reinterpret_cast<__half2*>(&vB1.y));
        float2 flo0 = __half22float2(lo0), fhi0 = __half22float2(hi0);
        float2 flo1 = __half22float2(lo1), fhi1 = __half22float2(hi1);
        a0x += flo0.x; a0y += flo0.y; a0z += fhi0.x; a0w += fhi0.y;
        a1x += flo1.x; a1y += flo1.y; a1z += fhi1.x; a1w += fhi1.y;
    }
    // reduce across the four quarters (each summed a different edge subset)
    #pragma unroll
    for (int o = 8; o <= 16; o <<= 1) {
        a0x += __shfl_xor_sync(0xffffffffu, a0x, o);
        a0y += __shfl_xor_sync(0xffffffffu, a0y, o);
        a0z += __shfl_xor_sync(0xffffffffu, a0z, o);
        a0w += __shfl_xor_sync(0xffffffffu, a0w, o);
        a1x += __shfl_xor_sync(0xffffffffu, a1x, o);
        a1y += __shfl_xor_sync(0xffffffffu, a1y, o);
        a1z += __shfl_xor_sync(0xffffffffu, a1z, o);
        a1w += __shfl_xor_sync(0xffffffffu, a1w, o);
    }
    // redistribute: feature k lives at lane (k>>2), component (k&3)
    int srcl = lane >> 2;
    float f0x = __shfl_sync(0xffffffffu, a0x, srcl);
    float f0y = __shfl_sync(0xffffffffu, a0y, srcl);
    float f0z = __shfl_sync(0xffffffffu, a0z, srcl);
    float f0w = __shfl_sync(0xffffffffu, a0w, srcl);
    float f1x = __shfl_sync(0xffffffffu, a1x, srcl);
    float f1y = __shfl_sync(0xffffffffu, a1y, srcl);
    float f1z = __shfl_sync(0xffffffffu, a1z, srcl);
    float f1w = __shfl_sync(0xffffffffu, a1w, srcl);
    int r = lane & 3;
    float accs0 = (r == 0) ? f0x : (r == 1) ? f0y : (r == 2) ? f0z : f0w;
    float accs1 = (r == 0) ? f1x : (r == 1) ? f1y : (r == 2) ? f1z : f1w;
    float dd0 = g_dinv[g0], dd1 = g_dinv[g1];
    float pr0 = -dd0 * accs0, pr1 = -dd1 * accs1;
    float tn0, tn1;
    if (PREV) {
        tn0 = 2.0f * pr0 - tprev[g0 * HID + lane];
        tn1 = 2.0f * pr1 - tprev[g1 * HID + lane];
    } else {
        tn0 = pr0; tn1 = pr1;
    }
    tout[g0 * HID + lane] = tn0;
    tout[g1 * HID + lane] = tn1;
    touth[g0 * HID + lane] = __float2half(dd0 * tn0);
    touth[g1 * HID + lane] = __float2half(dd1 * tn1);
    float o0 = g_O[g0 * HID + lane];
    float o1 = g_O[g1 * HID + lane];
    #pragma unroll
    for (int j = 0; j < 32; j++) {
        float w = Ws[j * 32 + lane];
        o0 = fmaf(__shfl_sync(0xffffffffu, tn0, j), w, o0);
        o1 = fmaf(__shfl_sync(0xffffffffu, tn1, j), w, o1);
    }
    g_O[g0 * HID + lane] = o0;
    g_O[g1 * HID + lane] = o1;
}

// finalize layer L + init layer L+1: h = relu(O + b); H=h; Hh=dinv*h; O = h @ Wn0
__global__ void __launch_bounds__(256, 6) k_finit(const float* __restrict__ b,
                                                  const float* __restrict__ Wn0) {
    __shared__ float Ws[1024];
    int tid = threadIdx.x;
    for (int j = tid; j < 1024; j += 256) Ws[j] = Wn0[j];
    __syncthreads();
    int gw = (blockIdx.x * 256 + tid) >> 5;
    int lane = tid & 31;
    float h = fmaxf(g_O[gw * HID + lane] + b[lane], 0.0f);
    g_H[gw * HID + lane] = h;
    g_Hh[gw * HID + lane] = __float2half(g_dinv[gw] * h);
    float oacc = 0.0f;
    #pragma unroll
    for (int j = 0; j < 32; j++)
        oacc = fmaf(__shfl_sync(0xffffffffu, h, j), Ws[j * 32 + lane], oacc);
    g_O[gw * HID + lane] = oacc;
}

// ---------------- final linear: (8, 262144) @ (262144, 33) + bl ----------------
// layer-3 bias b3 folded in (h = O + b3); no separate finalize pass.
__global__ void k_obias(const float* __restrict__ bl, float* __restrict__ out) {
    int i = threadIdx.x;
    if (i < NG * OC) out[i] = bl[i % OC];
}

__global__ void __launch_bounds__(288) k_linear(const float* __restrict__ Wl,
                                                const float* __restrict__ b3,
                                                float* __restrict__ out) {
    __shared__ float Ws[128 * OC];   // 16896 B
    __shared__ float hs[NG * 128];   //  4096 B
    int t = threadIdx.x;
    int i0 = blockIdx.x * 128;
    for (int j = t; j < 128 * OC; j += 288) Ws[j] = Wl[i0 * OC + j];
    for (int j = t; j < NG * 128; j += 288) {
        int g = j >> 7, ii = j & 127;
        hs[j] = g_O[g * (ISZ * HID) + i0 + ii] + b3[(i0 + ii) & 31];
    }
    __syncthreads();
    if (t < NG * OC) {
        int g = t / OC, o = t % OC;
        float acc = 0.0f;
        #pragma unroll 8
        for (int ii = 0; ii < 128; ii++)
            acc = fmaf(hs[g * 128 + ii], Ws[ii * OC + o], acc);
        atomicAdd(&out[g * OC + o], acc);
    }
}

// ---------------- host ----------------
extern "C" void kernel_launch(void* const* d_in, const int* in_sizes, int n_in,
                              void* d_out, int out_size) {
    const float* x  = (const float*)d_in[0];
    const int*   ei = (const int*)  d_in[1];
    const float* W1 = (const float*)d_in[3];
    const float* b1 = (const float*)d_in[4];
    const float* W2 = (const float*)d_in[5];
    const float* b2 = (const float*)d_in[6];
    const float* W3 = (const float*)d_in[7];
    const float* b3 = (const float*)d_in[8];
    const float* Wl = (const float*)d_in[9];
    const float* bl = (const float*)d_in[10];
    float* out = (float*)d_out;

    float *dH, *dA, *dB, *dC;
    float *dS1, *dS2, *dS3, *dS4, *dUx, *dU1, *dU2, *dU3, *dU4;
    __half *dHh, *dAh, *dBh, *dCh;
    cudaGetSymbolAddress((void**)&dH,  g_H);
    cudaGetSymbolAddress((void**)&dA,  g_A);
    cudaGetSymbolAddress((void**)&dB,  g_B);
    cudaGetSymbolAddress((void**)&dC,  g_C);
    cudaGetSymbolAddress((void**)&dHh, g_Hh);
    cudaGetSymbolAddress((void**)&dAh, g_Ah);
    cudaGetSymbolAddress((void**)&dBh, g_Bh);
    cudaGetSymbolAddress((void**)&dCh, g_Ch);
    cudaGetSymbolAddress((void**)&dS1, g_s1);
    cudaGetSymbolAddress((void**)&dS2, g_s2);
    cudaGetSymbolAddress((void**)&dS3, g_s3);
    cudaGetSymbolAddress((void**)&dS4, g_s4);
    cudaGetSymbolAddress((void**)&dUx, g_ux);
    cudaGetSymbolAddress((void**)&dU1, g_u1);
    cudaGetSymbolAddress((void**)&dU2, g_u2);
    cudaGetSymbolAddress((void**)&dU3, g_u3);
    cudaGetSymbolAddress((void**)&dU4, g_u4);

    const uint2 *dHh4 = (const uint2*)dHh;
    const uint2 *dAh4 = (const uint2*)dAh;
    const uint2 *dBh4 = (const uint2*)dBh;
    const uint2 *dCh4 = (const uint2*)dCh;

    // CSR build
    k_zero   <<<NN / 256, 256>>>();
    k_hist   <<<EE / 256, 256>>>(ei);
    k_scan1  <<<64, 1024>>>();                              // + pair-max cnt8 + dinv
    k_scan3  <<<NN / 256, 256>>>(x);                        // prefix + pad + u_x
    k_scatter<<<EE / 256, 256>>>(ei);

    // layer 1 (scalar Chebyshev recurrence, 4 nodes/warp)
    k_sprop<false><<<NN / 32, 256>>>(dUx, nullptr, dS1, dU1);
    k_sprop<true> <<<NN / 32, 256>>>(dU1, x,       dS2, dU2);
    k_sprop<true> <<<NN / 32, 256>>>(dU2, dS1,     dS3, dU3);
    k_sprop<true> <<<NN / 32, 256>>>(dU3, dS2,     dS4, dU4);
    k_l1init<<<NN / 8, 256>>>(x, W1, b1, W2);

    // layer 2 (dual-node prop: NN/2 warps -> NN/16 blocks)
    k_prop32<false> <<<NN / 16, 256>>>(dHh4, nullptr, dA, dAh, W2 + 1 * 1024);
    k_prop32<true>  <<<NN / 16, 256>>>(dAh4, dH,      dB, dBh, W2 + 2 * 1024);
    k_prop32<true>  <<<NN / 16, 256>>>(dBh4, dA,      dC, dCh, W2 + 3 * 1024);
    k_prop32<true>  <<<NN / 16, 256>>>(dCh4, dB,      dA, dAh, W2 + 4 * 1024);
    k_finit<<<NN / 8, 256>>>(b2, W3);   // relu + layer-3 init

    // layer 3
    k_prop32<false> <<<NN / 16, 256>>>(dHh4, nullptr, dA, dAh, W3 + 1 * 1024);
    k_prop32<true>  <<<NN / 16, 256>>>(dAh4, dH,      dB, dBh, W3 + 2 * 1024);
    k_prop32<true>  <<<NN / 16, 256>>>(dBh4, dA,      dC, dCh, W3 + 3 * 1024);
    k_prop32<true>  <<<NN / 16, 256>>>(dCh4, dB,      dA, dAh, W3 + 4 * 1024);

    // readout (b3 folded into k_linear)
    k_obias <<<1, 288>>>(bl, out);
    k_linear<<<(ISZ * HID) / 128, 288>>>(Wl, b3, out);
}

// round 17
// speedup vs baseline: 1.2679x; 1.1089x over previous
#include <cuda_runtime.h>
#include <cuda_fp16.h>

#define NN 65536
#define EE 2097152
#define EPAD (2 * EE + 16 * NN)
#define HID 32
#define NG 8
#define OC 33
#define ISZ 8192

// ---------------- scratch (static device allocations only) ----------------
__device__ int   g_deg[NN];
__device__ float g_dinv[NN];
__device__ int   g_cnt[NN];      // raw dst-degree
__device__ int   g_cnt8[NN];     // pair-equalized, padded to multiple of 8
__device__ int   g_rowptr[NN];   // exclusive scan of padded counts (mult of 8)
__device__ int   g_wp[NN];
__device__ int   g_bsum[64];
__device__ __align__(16) int g_esrc[EPAD];   // src-only edges (norm factored out)
// scalar t values (fp32) and premultiplied gather values u = dinv*t (fp32)
__device__ float g_s1[NN], g_s2[NN], g_s3[NN], g_s4[NN];
__device__ float g_ux[NN + 8], g_u1[NN + 8], g_u2[NN + 8], g_u3[NN + 8], g_u4[NN + 8];
__device__ __align__(128) float g_H[NN * HID];
__device__ __align__(128) float g_A[NN * HID];
__device__ __align__(128) float g_B[NN * HID];
__device__ __align__(128) float g_C[NN * HID];
__device__ __align__(128) float g_O[NN * HID];
// fp16 premultiplied gather mirrors: row i < NN holds dinv[i]*t[i]; rows >= NN
// are NEVER written -> remain statically zero-initialized (pad sentinel src=NN)
__device__ __align__(128) __half g_Hh[(NN + 8) * HID];
__device__ __align__(128) __half g_Ah[(NN + 8) * HID];
__device__ __align__(128) __half g_Bh[(NN + 8) * HID];
__device__ __align__(128) __half g_Ch[(NN + 8) * HID];

// ---------------- CSR build ----------------
__global__ void k_zero() {
    int i = blockIdx.x * blockDim.x + threadIdx.x;
    if (i < NN) { g_deg[i] = 0; g_cnt[i] = 0; }
}

__global__ void k_hist(const int* __restrict__ ei) {
    int e = blockIdx.x * blockDim.x + threadIdx.x;
    if (e < EE) {
        atomicAdd(&g_deg[ei[e]], 1);        // degree by src
        atomicAdd(&g_cnt[ei[EE + e]], 1);   // histogram by dst
    }
}

// block-level inclusive scan of pair-equalized padded counts + fused dinv.
// Node pair (2k, 2k+1) both get align8(max(cnt[2k], cnt[2k+1])) slots so the
// dual-node prop loop needs no per-node predication.
__global__ void k_scan1() {
    __shared__ int wsum[32];
    int t = threadIdx.x, b = blockIdx.x;
    int i = b * 1024 + t;
    int lane = t & 31, w = t >> 5;
    int d = g_deg[i];
    g_dinv[i] = (d > 0) ? rsqrtf((float)d) : 0.0f;

    int ca = g_cnt[i];
    int cb = g_cnt[i ^ 1];                  // pair partner (same block)
    int cm = ca > cb ? ca : cb;
    int cntp = (cm + 7) & ~7;
    g_cnt8[i] = cntp;

    int x = cntp;
    #pragma unroll
    for (int o = 1; o < 32; o <<= 1) {
        int y = __shfl_up_sync(0xffffffffu, x, o);
        if (lane >= o) x += y;
    }
    if (lane == 31) wsum[w] = x;
    __syncthreads();
    if (w == 0) {
        int s = wsum[lane];
        #pragma unroll
        for (int o = 1; o < 32; o <<= 1) {
            int y = __shfl_up_sync(0xffffffffu, s, o);
            if (lane >= o) s += y;
        }
        wsum[lane] = s;
    }
    __syncthreads();
    int incl = x + (w > 0 ? wsum[w - 1] : 0);
    g_rowptr[i] = incl;                 // inclusive-within-block (temp)
    if (t == 1023) g_bsum[b] = incl;
}

// finalize rowptr (cross-block prefix inline), fill pad slots, compute u_x
__global__ void k_scan3(const float* __restrict__ x) {
    __shared__ int prefix;
    int i = blockIdx.x * 256 + threadIdx.x;
    if (threadIdx.x == 0) {
        int bchunk = blockIdx.x >> 2;   // 1024-node chunks
        int s = 0;
        for (int j = 0; j < bchunk; j++) s += g_bsum[j];
        prefix = s;
    }
    __syncthreads();
    int excl = g_rowptr[i] - g_cnt8[i] + prefix;   // multiple of 8
    g_rowptr[i] = excl;
    g_wp[i] = excl;
    g_ux[i] = g_dinv[i] * x[i];
    int c = g_cnt[i], cp = g_cnt8[i];
    for (int j = excl + c; j < excl + cp; j++) g_esrc[j] = NN;  // zero-row sentinel
}

__global__ void k_scatter(const int* __restrict__ ei) {
    int e = blockIdx.x * blockDim.x + threadIdx.x;
    if (e < EE) {
        int d = ei[EE + e];
        int pos = atomicAdd(&g_wp[d], 1);
        g_esrc[pos] = ei[e];
    }
}

// ---------------- layer 1 (scalar features, premultiplied gathers) ----------------
// FOUR nodes per warp, 8 lanes each; int4 edge loads (4 edges/lane/iter).
template <bool PREV>
__global__ void k_sprop(const float* __restrict__ uin,
                        const float* __restrict__ sprev,
                        float* __restrict__ sout,
                        float* __restrict__ usout) {
    int warp = (blockIdx.x * blockDim.x + threadIdx.x) >> 5;
    int lane = threadIdx.x & 31;
    int sub = lane & 7;                      // lane within 8-lane group
    int node = warp * 4 + (lane >> 3);       // group -> node
    int beg = g_rowptr[node], c = g_cnt8[node];
    float acc = 0.0f;
    for (int j = sub * 4; j < c; j += 32) {
        int4 s4 = *reinterpret_cast<const int4*>(g_esrc + beg + j);
        acc += (__ldg(&uin[s4.x]) + __ldg(&uin[s4.y]))
             + (__ldg(&uin[s4.z]) + __ldg(&uin[s4.w]));
    }
    #pragma unroll
    for (int o = 4; o; o >>= 1) acc += __shfl_xor_sync(0xffffffffu, acc, o);
    if (sub == 0) {
        float dd = g_dinv[node];
        float p = -dd * acc;
        float tn = PREV ? (2.0f * p - sprev[node]) : p;
        sout[node] = tn;
        usout[node] = dd * tn;
    }
}

// layer-1 combine + layer-2 init: h = relu(b1 + sum_k s_k*W1[k]); H=h; Hh=dinv*h; O = h @ W2[0]
__global__ void __launch_bounds__(256, 6) k_l1init(const float* __restrict__ x,
                                                   const float* __restrict__ W1,
                                                   const float* __restrict__ b1,
                                                   const float* __restrict__ W20) {
    int tid = threadIdx.x;
    int gw = (blockIdx.x * 256 + tid) >> 5;
    int lane = tid & 31;
    float v = b1[lane]
            + x[gw]      * W1[lane]
            + g_s1[gw]   * W1[32 + lane]
            + g_s2[gw]   * W1[64 + lane]
            + g_s3[gw]   * W1[96 + lane]
            + g_s4[gw]   * W1[128 + lane];
    float h = fmaxf(v, 0.0f);
    g_H[gw * HID + lane] = h;
    g_Hh[gw * HID + lane] = __float2half(g_dinv[gw] * h);
    float oacc = 0.0f;
    #pragma unroll
    for (int j = 0; j < 32; j++)
        oacc = fmaf(__shfl_sync(0xffffffffu, h, j), __ldg(&W20[j * 32 + lane]), oacc);
    g_O[gw * HID + lane] = oacc;
}

// ---------------- layers 2/3 (32-wide), TWO nodes per warp ----------------
// Quarter-warp packed fp16 gathers (one LDG.64 covers 4 edges). No shared
// memory, no __syncthreads: epilogue W reads go through __ldg (4KB, L1-hot).
// WRT=false (t4 props) skips tout/touth writes: t4 is never gathered and
// never used as tprev -- only its epilogue contribution to g_O matters.
template <bool PREV, bool WRT>
__global__ void __launch_bounds__(256, 6) k_prop32(const uint2* __restrict__ tin4,
                                                   const float* __restrict__ tprev,
                                                   float* __restrict__ tout,
                                                   __half* __restrict__ touth,
                                                   const float* __restrict__ Wk) {
    int tid = threadIdx.x;
    int warp = (blockIdx.x * 256 + tid) >> 5;
    int g0 = warp * 2, g1 = g0 + 1;
    int lane = tid & 31;
    int q = lane >> 3;                       // quarter id: which edge of 4
    int sub = lane & 7;                      // uint2 index within 32-feature row
    const int* e0 = g_esrc + g_rowptr[g0];
    const int* e1 = g_esrc + g_rowptr[g1];
    int nIter = g_cnt8[g0] >> 3;             // == g_cnt8[g1] >> 3 (pair-equalized)
    float a0x = 0.f, a0y = 0.f, a0z = 0.f, a0w = 0.f;
    float a1x = 0.f, a1y = 0.f, a1z = 0.f, a1w = 0.f;
    for (int it = 0; it < nIter; it++) {
        int sA0 = __ldg(e0 + q);             // edges 0..3 of g0 (broadcast/quarter)
        int sB0 = __ldg(e0 + 4 + q);         // edges 4..7 of g0
        int sA1 = __ldg(e1 + q);
        int sB1 = __ldg(e1 + 4 + q);
        e0 += 8; e1 += 8;
        uint2 vA0 = __ldg(tin4 + sA0 * 8 + sub);
        uint2 vB0 = __ldg(tin4 + sB0 * 8 + sub);
        uint2 vA1 = __ldg(tin4 + sA1 * 8 + sub);
        uint2 vB1 = __ldg(tin4 + sB1 * 8 + sub);
        __half2 lo0 = __hadd2(*reinterpret_cast<__half2*>(&vA0.x),
                              *reinterpret_cast<__half2*>(&vB0.x));
        __half2 hi0 = __hadd2(*reinterpret_cast<__half2*>(&vA0.y),
                              *reinterpret_cast<__half2*>(&vB0.y));
        __half2 lo1 = __hadd2(*reinterpret_cast<__half2*>(&vA1.x),
                              *reinterpret_cast<__half2*>(&vB1.x));
        __half2 hi1 = __hadd2(*reinterpret_cast<__half2*>(&vA1.y),
                              *reinterpret_cast<__half2*>(&vB1.y));
        float2 flo0 = __half22float2(lo0), fhi0 = __half22float2(hi0);
        float2 flo1 = __half22float2(lo1), fhi1 = __half22float2(hi1);
        a0x += flo0.x; a0y += flo0.y; a0z += fhi0.x; a0w += fhi0.y;
        a1x += flo1.x; a1y += flo1.y; a1z += fhi1.x; a1w += fhi1.y;
    }
    // reduce across the four quarters (each summed a different edge subset)
    #pragma unroll
    for (int o = 8; o <= 16; o <<= 1) {
        a0x += __shfl_xor_sync(0xffffffffu, a0x, o);
        a0y += __shfl_xor_sync(0xffffffffu, a0y, o);
        a0z += __shfl_xor_sync(0xffffffffu, a0z, o);
        a0w += __shfl_xor_sync(0xffffffffu, a0w, o);
        a1x += __shfl_xor_sync(0xffffffffu, a1x, o);
        a1y += __shfl_xor_sync(0xffffffffu, a1y, o);
        a1z += __shfl_xor_sync(0xffffffffu, a1z, o);
        a1w += __shfl_xor_sync(0xffffffffu, a1w, o);
    }
    // redistribute: feature k lives at lane (k>>2), component (k&3)
    int srcl = lane >> 2;
    float f0x = __shfl_sync(0xffffffffu, a0x, srcl);
    float f0y = __shfl_sync(0xffffffffu, a0y, srcl);
    float f0z = __shfl_sync(0xffffffffu, a0z, srcl);
    float f0w = __shfl_sync(0xffffffffu, a0w, srcl);
    float f1x = __shfl_sync(0xffffffffu, a1x, srcl);
    float f1y = __shfl_sync(0xffffffffu, a1y, srcl);
    float f1z = __shfl_sync(0xffffffffu, a1z, srcl);
    float f1w = __shfl_sync(0xffffffffu, a1w, srcl);
    int r = lane & 3;
    float accs0 = (r == 0) ? f0x : (r == 1) ? f0y : (r == 2) ? f0z : f0w;
    float accs1 = (r == 0) ? f1x : (r == 1) ? f1y : (r == 2) ? f1z : f1w;
    float dd0 = g_dinv[g0], dd1 = g_dinv[g1];
    float pr0 = -dd0 * accs0, pr1 = -dd1 * accs1;
    float tn0, tn1;
    if (PREV) {
        tn0 = 2.0f * pr0 - tprev[g0 * HID + lane];
        tn1 = 2.0f * pr1 - tprev[g1 * HID + lane];
    } else {
        tn0 = pr0; tn1 = pr1;
    }
    if (WRT) {
        tout[g0 * HID + lane] = tn0;
        tout[g1 * HID + lane] = tn1;
        touth[g0 * HID + lane] = __float2half(dd0 * tn0);
        touth[g1 * HID + lane] = __float2half(dd1 * tn1);
    }
    float o0 = g_O[g0 * HID + lane];
    float o1 = g_O[g1 * HID + lane];
    #pragma unroll
    for (int j = 0; j < 32; j++) {
        float w = __ldg(&Wk[j * 32 + lane]);
        o0 = fmaf(__shfl_sync(0xffffffffu, tn0, j), w, o0);
        o1 = fmaf(__shfl_sync(0xffffffffu, tn1, j), w, o1);
    }
    g_O[g0 * HID + lane] = o0;
    g_O[g1 * HID + lane] = o1;
}

// finalize layer L + init layer L+1: h = relu(O + b); H=h; Hh=dinv*h; O = h @ Wn0
__global__ void __launch_bounds__(256, 6) k_finit(const float* __restrict__ b,
                                                  const float* __restrict__ Wn0) {
    int tid = threadIdx.x;
    int gw = (blockIdx.x * 256 + tid) >> 5;
    int lane = tid & 31;
    float h = fmaxf(g_O[gw * HID + lane] + b[lane], 0.0f);
    g_H[gw * HID + lane] = h;
    g_Hh[gw * HID + lane] = __float2half(g_dinv[gw] * h);
    float oacc = 0.0f;
    #pragma unroll
    for (int j = 0; j < 32; j++)
        oacc = fmaf(__shfl_sync(0xffffffffu, h, j), __ldg(&Wn0[j * 32 + lane]), oacc);
    g_O[gw * HID + lane] = oacc;
}

// ---------------- final linear: (8, 262144) @ (262144, 33) + bl ----------------
// layer-3 bias b3 folded in (h = O + b3); no separate finalize pass.
__global__ void k_obias(const float* __restrict__ bl, float* __restrict__ out) {
    int i = threadIdx.x;
    if (i < NG * OC) out[i] = bl[i % OC];
}

__global__ void __launch_bounds__(288) k_linear(const float* __restrict__ Wl,
                                                const float* __restrict__ b3,
                                                float* __restrict__ out) {
    __shared__ float Ws[128 * OC];   // 16896 B
    __shared__ float hs[NG * 128];   //  4096 B
    int t = threadIdx.x;
    int i0 = blockIdx.x * 128;
    for (int j = t; j < 128 * OC; j += 288) Ws[j] = Wl[i0 * OC + j];
    for (int j = t; j < NG * 128; j += 288) {
        int g = j >> 7, ii = j & 127;
        hs[j] = g_O[g * (ISZ * HID) + i0 + ii] + b3[(i0 + ii) & 31];
    }
    __syncthreads();
    if (t < NG * OC) {
        int g = t / OC, o = t % OC;
        float acc = 0.0f;
        #pragma unroll 8
        for (int ii = 0; ii < 128; ii++)
            acc = fmaf(hs[g * 128 + ii], Ws[ii * OC + o], acc);
        atomicAdd(&out[g * OC + o], acc);
    }
}

// ---------------- host ----------------
extern "C" void kernel_launch(void* const* d_in, const int* in_sizes, int n_in,
                              void* d_out, int out_size) {
    const float* x  = (const float*)d_in[0];
    const int*   ei = (const int*)  d_in[1];
    const float* W1 = (const float*)d_in[3];
    const float* b1 = (const float*)d_in[4];
    const float* W2 = (const float*)d_in[5];
    const float* b2 = (const float*)d_in[6];
    const float* W3 = (const float*)d_in[7];
    const float* b3 = (const float*)d_in[8];
    const float* Wl = (const float*)d_in[9];
    const float* bl = (const float*)d_in[10];
    float* out = (float*)d_out;

    float *dH, *dA, *dB, *dC;
    float *dS1, *dS2, *dS3, *dS4, *dUx, *dU1, *dU2, *dU3, *dU4;
    __half *dHh, *dAh, *dBh, *dCh;
    cudaGetSymbolAddress((void**)&dH,  g_H);
    cudaGetSymbolAddress((void**)&dA,  g_A);
    cudaGetSymbolAddress((void**)&dB,  g_B);
    cudaGetSymbolAddress((void**)&dC,  g_C);
    cudaGetSymbolAddress((void**)&dHh, g_Hh);
    cudaGetSymbolAddress((void**)&dAh, g_Ah);
    cudaGetSymbolAddress((void**)&dBh, g_Bh);
    cudaGetSymbolAddress((void**)&dCh, g_Ch);
    cudaGetSymbolAddress((void**)&dS1, g_s1);
    cudaGetSymbolAddress((void**)&dS2, g_s2);
    cudaGetSymbolAddress((void**)&dS3, g_s3);
    cudaGetSymbolAddress((void**)&dS4, g_s4);
    cudaGetSymbolAddress((void**)&dUx, g_ux);
    cudaGetSymbolAddress((void**)&dU1, g_u1);
    cudaGetSymbolAddress((void**)&dU2, g_u2);
    cudaGetSymbolAddress((void**)&dU3, g_u3);
    cudaGetSymbolAddress((void**)&dU4, g_u4);

    const uint2 *dHh4 = (const uint2*)dHh;
    const uint2 *dAh4 = (const uint2*)dAh;
    const uint2 *dBh4 = (const uint2*)dBh;
    const uint2 *dCh4 = (const uint2*)dCh;

    // CSR build
    k_zero   <<<NN / 256, 256>>>();
    k_hist   <<<EE / 256, 256>>>(ei);
    k_scan1  <<<64, 1024>>>();                              // + pair-max cnt8 + dinv
    k_scan3  <<<NN / 256, 256>>>(x);                        // prefix + pad + u_x
    k_scatter<<<EE / 256, 256>>>(ei);

    // layer 1 (scalar Chebyshev recurrence, 4 nodes/warp)
    k_sprop<false><<<NN / 32, 256>>>(dUx, nullptr, dS1, dU1);
    k_sprop<true> <<<NN / 32, 256>>>(dU1, x,       dS2, dU2);
    k_sprop<true> <<<NN / 32, 256>>>(dU2, dS1,     dS3, dU3);
    k_sprop<true> <<<NN / 32, 256>>>(dU3, dS2,     dS4, dU4);
    k_l1init<<<NN / 8, 256>>>(x, W1, b1, W2);

    // layer 2 (dual-node prop: NN/2 warps -> NN/16 blocks)
    k_prop32<false, true> <<<NN / 16, 256>>>(dHh4, nullptr, dA, dAh, W2 + 1 * 1024);
    k_prop32<true,  true> <<<NN / 16, 256>>>(dAh4, dH,      dB, dBh, W2 + 2 * 1024);
    k_prop32<true,  true> <<<NN / 16, 256>>>(dBh4, dA,      dC, dCh, W2 + 3 * 1024);
    k_prop32<true,  false><<<NN / 16, 256>>>(dCh4, dB,  nullptr, nullptr, W2 + 4 * 1024);
    k_finit<<<NN / 8, 256>>>(b2, W3);   // relu + layer-3 init

    // layer 3
    k_prop32<false, true> <<<NN / 16, 256>>>(dHh4, nullptr, dA, dAh, W3 + 1 * 1024);
    k_prop32<true,  true> <<<NN / 16, 256>>>(dAh4, dH,      dB, dBh, W3 + 2 * 1024);
    k_prop32<true,  true> <<<NN / 16, 256>>>(dBh4, dA,      dC, dCh, W3 + 3 * 1024);
    k_prop32<true,  false><<<NN / 16, 256>>>(dCh4, dB,  nullptr, nullptr, W3 + 4 * 1024);

    // readout (b3 folded into k_linear)
    k_obias <<<1, 288>>>(bl, out);
    k_linear<<<(ISZ * HID) / 128, 288>>>(Wl, b3, out);
}